// round 3
// baseline (speedup 1.0000x reference)
#include <cuda_runtime.h>
#include <cuda_bf16.h>
#include <math.h>

#define NN 15840        // nodes
#define EE 253440       // edges
#define BB 48           // graphs
#define HID 256
#define INCH 128

// ---------------- scratch ----------------
__device__ float g_xn[NN * INCH];
__device__ float g_q[NN * HID];
__device__ float g_k[NN * HID];
__device__ float g_v[NN * HID];
__device__ float g_skip[NN * HID];
__device__ float g_out[NN * HID];
__device__ int   g_cnt[NN];
__device__ int   g_cur[NN];
__device__ int   g_ofs[NN + 1];
__device__ int   g_ssrc[EE];
__device__ int   g_seid[EE];
__device__ float g_bnsum[HID];
__device__ float g_bnsumsq[HID];
__device__ float g_scale[HID];
__device__ float g_shift[HID];
__device__ float g_pool[BB * 18 * HID];
__device__ float g_bacc[BB];

__device__ __forceinline__ unsigned f2tf(float f) {
    unsigned r;
    asm("cvt.rna.tf32.f32 %0, %1;" : "=r"(r) : "f"(f));
    return r;
}

// ---------------- init ----------------
__global__ void k_init() {
    int i = blockIdx.x * blockDim.x + threadIdx.x;
    int stride = gridDim.x * blockDim.x;
    for (int t = i; t < NN; t += stride) { g_cnt[t] = 0; g_cur[t] = 0; }
    if (i < HID) { g_bnsum[i] = 0.f; g_bnsumsq[i] = 0.f; }
    if (i < BB) g_bacc[i] = 0.f;
}

// ---------------- CSR build ----------------
__global__ __launch_bounds__(256) void k_count(const int* __restrict__ ei) {
    int e = blockIdx.x * 256 + threadIdx.x;
    if (e < EE) atomicAdd(&g_cnt[ei[EE + e]], 1);
}

__global__ __launch_bounds__(1024) void k_scan() {
    __shared__ int warpsum[32];
    int t = threadIdx.x;
    int base = t * 16;
    int loc[16];
    int s = 0;
    #pragma unroll
    for (int i = 0; i < 16; i++) {
        int idx = base + i;
        int c = (idx < NN) ? g_cnt[idx] : 0;
        loc[i] = s; s += c;
    }
    int lane = t & 31, wid = t >> 5;
    int v = s;
    #pragma unroll
    for (int o = 1; o < 32; o <<= 1) {
        int n = __shfl_up_sync(~0u, v, o);
        if (lane >= o) v += n;
    }
    if (lane == 31) warpsum[wid] = v;
    __syncthreads();
    if (wid == 0) {
        int w = warpsum[lane];
        #pragma unroll
        for (int o = 1; o < 32; o <<= 1) {
            int n = __shfl_up_sync(~0u, w, o);
            if (lane >= o) w += n;
        }
        warpsum[lane] = w;
    }
    __syncthreads();
    int offset = (v - s) + (wid ? warpsum[wid - 1] : 0);
    #pragma unroll
    for (int i = 0; i < 16; i++) {
        int idx = base + i;
        if (idx < NN) g_ofs[idx] = offset + loc[i];
    }
    if (t == 1023) g_ofs[NN] = offset + s;
}

__global__ __launch_bounds__(256) void k_fill(const int* __restrict__ ei) {
    int e = blockIdx.x * 256 + threadIdx.x;
    if (e >= EE) return;
    int d = ei[EE + e];
    int pos = atomicAdd(&g_cur[d], 1);
    int slot = g_ofs[d] + pos;
    g_ssrc[slot] = ei[e];
    g_seid[slot] = e;
}

// ---------------- LayerNorm over 128 features ----------------
__global__ __launch_bounds__(128) void k_ln(const float* __restrict__ x,
                                            const float* __restrict__ lg,
                                            const float* __restrict__ lb) {
    int row = blockIdx.x;
    int c = threadIdx.x;
    float v = x[row * INCH + c];
    __shared__ float sm[4];
    float s = v;
    #pragma unroll
    for (int o = 16; o; o >>= 1) s += __shfl_xor_sync(~0u, s, o);
    int wid = c >> 5, lane = c & 31;
    if (lane == 0) sm[wid] = s;
    __syncthreads();
    float mean = (sm[0] + sm[1] + sm[2] + sm[3]) * (1.f / 128.f);
    float d = v - mean;
    float s2 = d * d;
    #pragma unroll
    for (int o = 16; o; o >>= 1) s2 += __shfl_xor_sync(~0u, s2, o);
    __syncthreads();
    if (lane == 0) sm[wid] = s2;
    __syncthreads();
    float var = (sm[0] + sm[1] + sm[2] + sm[3]) * (1.f / 128.f);
    g_xn[row * INCH + c] = d * rsqrtf(var + 1e-5f) * lg[c] + lb[c];
}

// ---------------- tf32 tensor-core GEMM: xn[N,128] @ W^T -> {q,k,v,skip} ----------------
// Block: 128 threads (4 warps). Tile: M=32, N=128, K=128 (chunks of 32).
// Each warp: 32x32 warp tile = 2 (m16) x 4 (n8) mma.m16n8k8 frags.
__global__ __launch_bounds__(128) void k_gemm(const float* __restrict__ Wq, const float* __restrict__ bq,
                                              const float* __restrict__ Wk, const float* __restrict__ bk,
                                              const float* __restrict__ Wv, const float* __restrict__ bv,
                                              const float* __restrict__ Ws, const float* __restrict__ bs) {
    __shared__ unsigned As[32][33];
    __shared__ unsigned Bs[128][33];
    __shared__ float sbias[128];

    int bn0 = blockIdx.x * 128;          // global out col base (0..1023)
    int m0  = blockIdx.y * 32;
    int g = bn0 >> 8;
    const float* W; const float* bias; float* out;
    if (g == 0)      { W = Wq; bias = bq; out = g_q; }
    else if (g == 1) { W = Wk; bias = bk; out = g_k; }
    else if (g == 2) { W = Wv; bias = bv; out = g_v; }
    else             { W = Ws; bias = bs; out = g_skip; }
    int lc0 = bn0 & 255;                 // local col base within [0,256)

    int tid = threadIdx.x;
    int lane = tid & 31, warp = tid >> 5;
    int wn0 = warp * 32;                 // warp col base within tile

    if (tid < 128) sbias[tid] = bias[lc0 + tid];

    float acc[2][4][4];
    #pragma unroll
    for (int mi = 0; mi < 2; mi++)
        #pragma unroll
        for (int ni = 0; ni < 4; ni++)
            #pragma unroll
            for (int r = 0; r < 4; r++) acc[mi][ni][r] = 0.f;

    for (int kt = 0; kt < 4; kt++) {
        int k0 = kt * 32;
        // A tile: rows m0..+32, cols k0..+32. thread t: row t>>2, cols (t&3)*8..+8
        {
            int r = tid >> 2;
            int cc = (tid & 3) * 8;
            const float4* src = (const float4*)(g_xn + (size_t)(m0 + r) * INCH + k0 + cc);
            float4 x0 = src[0], x1 = src[1];
            As[r][cc + 0] = f2tf(x0.x); As[r][cc + 1] = f2tf(x0.y);
            As[r][cc + 2] = f2tf(x0.z); As[r][cc + 3] = f2tf(x0.w);
            As[r][cc + 4] = f2tf(x1.x); As[r][cc + 5] = f2tf(x1.y);
            As[r][cc + 6] = f2tf(x1.z); As[r][cc + 7] = f2tf(x1.w);
        }
        // B tile: Bs[n][k], n 0..127 (thread), k 0..31
        {
            const float4* src = (const float4*)(W + (size_t)(lc0 + tid) * INCH + k0);
            #pragma unroll
            for (int c4 = 0; c4 < 8; c4++) {
                float4 w4 = src[c4];
                Bs[tid][c4 * 4 + 0] = f2tf(w4.x);
                Bs[tid][c4 * 4 + 1] = f2tf(w4.y);
                Bs[tid][c4 * 4 + 2] = f2tf(w4.z);
                Bs[tid][c4 * 4 + 3] = f2tf(w4.w);
            }
        }
        __syncthreads();

        #pragma unroll
        for (int ks = 0; ks < 4; ks++) {
            int kk = ks * 8;
            int ar = lane >> 2, ac = kk + (lane & 3);
            unsigned a[2][4];
            #pragma unroll
            for (int mi = 0; mi < 2; mi++) {
                int r = mi * 16 + ar;
                a[mi][0] = As[r][ac];
                a[mi][1] = As[r + 8][ac];
                a[mi][2] = As[r][ac + 4];
                a[mi][3] = As[r + 8][ac + 4];
            }
            #pragma unroll
            for (int ni = 0; ni < 4; ni++) {
                int n = wn0 + ni * 8 + (lane >> 2);
                unsigned b0 = Bs[n][kk + (lane & 3)];
                unsigned b1 = Bs[n][kk + (lane & 3) + 4];
                #pragma unroll
                for (int mi = 0; mi < 2; mi++) {
                    asm volatile(
                        "mma.sync.aligned.m16n8k8.row.col.f32.tf32.tf32.f32 "
                        "{%0,%1,%2,%3}, {%4,%5,%6,%7}, {%8,%9}, {%0,%1,%2,%3};"
                        : "+f"(acc[mi][ni][0]), "+f"(acc[mi][ni][1]),
                          "+f"(acc[mi][ni][2]), "+f"(acc[mi][ni][3])
                        : "r"(a[mi][0]), "r"(a[mi][1]), "r"(a[mi][2]), "r"(a[mi][3]),
                          "r"(b0), "r"(b1));
                }
            }
        }
        __syncthreads();
    }

    // epilogue
    #pragma unroll
    for (int mi = 0; mi < 2; mi++) {
        #pragma unroll
        for (int ni = 0; ni < 4; ni++) {
            int col = lc0 + wn0 + ni * 8 + 2 * (lane & 3);
            int row0 = m0 + mi * 16 + (lane >> 2);
            float b0 = sbias[col - lc0], b1 = sbias[col - lc0 + 1];
            float2 v0 = make_float2(acc[mi][ni][0] + b0, acc[mi][ni][1] + b1);
            float2 v1 = make_float2(acc[mi][ni][2] + b0, acc[mi][ni][3] + b1);
            *(float2*)(out + (size_t)row0 * HID + col) = v0;
            *(float2*)(out + (size_t)(row0 + 8) * HID + col) = v1;
        }
    }
}

// ---------------- fused attention: online softmax gather per node ----------------
__global__ __launch_bounds__(256) void k_agg(const float* __restrict__ ea,
                                             const float* __restrict__ We) {
    __shared__ float sWe[HID * 5];
    for (int t = threadIdx.x; t < HID * 5; t += 256) sWe[t] = We[t];
    __syncthreads();
    int node = blockIdx.x * 8 + (threadIdx.x >> 5);
    if (node >= NN) return;
    int lane = threadIdx.x & 31;
    int c0 = lane * 8;
    int beg = g_ofs[node], end = g_ofs[node + 1];

    const float4* qp = (const float4*)(g_q + (size_t)node * HID + c0);
    float4 q0 = qp[0], q1 = qp[1];

    // qWe[j] = sum_c q[c] * We[c][j]  (fused, q already in regs)
    float qw[5] = {};
    {
        float qv[8] = {q0.x, q0.y, q0.z, q0.w, q1.x, q1.y, q1.z, q1.w};
        #pragma unroll
        for (int u = 0; u < 8; u++) {
            int c = c0 + u;
            #pragma unroll
            for (int j = 0; j < 5; j++) qw[j] += qv[u] * sWe[c * 5 + j];
        }
        #pragma unroll
        for (int j = 0; j < 5; j++) {
            #pragma unroll
            for (int o = 16; o; o >>= 1) qw[j] += __shfl_xor_sync(~0u, qw[j], o);
        }
    }

    float m = -1e30f;
    float z = 0.f;
    float acc[8] = {};
    float ae0 = 0.f, ae1 = 0.f, ae2 = 0.f, ae3 = 0.f, ae4 = 0.f;

    for (int a = beg; a < end; a++) {
        int s = g_ssrc[a];
        int eid = g_seid[a];
        const float* eap = ea + (size_t)eid * 5;
        float e0 = eap[0], e1 = eap[1], e2 = eap[2], e3 = eap[3], e4 = eap[4];
        const float4* kp = (const float4*)(g_k + (size_t)s * HID + c0);
        float4 k0 = kp[0], k1 = kp[1];
        const float4* vp = (const float4*)(g_v + (size_t)s * HID + c0);
        float4 v0 = vp[0], v1 = vp[1];

        float dot = q0.x * k0.x + q0.y * k0.y + q0.z * k0.z + q0.w * k0.w
                  + q1.x * k1.x + q1.y * k1.y + q1.z * k1.z + q1.w * k1.w;
        #pragma unroll
        for (int o = 16; o; o >>= 1) dot += __shfl_xor_sync(~0u, dot, o);
        float alpha = (dot + qw[0] * e0 + qw[1] * e1 + qw[2] * e2 + qw[3] * e3 + qw[4] * e4) * 0.0625f;

        float nm = fmaxf(m, alpha);
        float sc = __expf(m - nm);
        float w  = __expf(alpha - nm);
        m = nm;
        z = z * sc + w;
        acc[0] = acc[0] * sc + w * v0.x;
        acc[1] = acc[1] * sc + w * v0.y;
        acc[2] = acc[2] * sc + w * v0.z;
        acc[3] = acc[3] * sc + w * v0.w;
        acc[4] = acc[4] * sc + w * v1.x;
        acc[5] = acc[5] * sc + w * v1.y;
        acc[6] = acc[6] * sc + w * v1.z;
        acc[7] = acc[7] * sc + w * v1.w;
        ae0 = ae0 * sc + w * e0;
        ae1 = ae1 * sc + w * e1;
        ae2 = ae2 * sc + w * e2;
        ae3 = ae3 * sc + w * e3;
        ae4 = ae4 * sc + w * e4;
    }

    float inv = 1.f / (z + 1e-16f);
    const float* skp = g_skip + (size_t)node * HID + c0;
    float* op = g_out + (size_t)node * HID + c0;
    #pragma unroll
    for (int u = 0; u < 8; u++) {
        int c = c0 + u;
        float ev = sWe[c * 5 + 0] * ae0 + sWe[c * 5 + 1] * ae1 + sWe[c * 5 + 2] * ae2
                 + sWe[c * 5 + 3] * ae3 + sWe[c * 5 + 4] * ae4;
        op[u] = (acc[u] + ev) * inv + skp[u];
    }
}

// ---------------- BN stats ----------------
__global__ __launch_bounds__(256) void k_bnstat() {
    int row0 = blockIdx.x * 32;
    int c = threadIdx.x;
    float s1 = 0.f, s2 = 0.f;
    for (int r = 0; r < 32; r++) {
        int row = row0 + r;
        if (row >= NN) break;
        float v = g_out[row * HID + c];
        s1 += v; s2 += v * v;
    }
    atomicAdd(&g_bnsum[c], s1);
    atomicAdd(&g_bnsumsq[c], s2);
}

__global__ __launch_bounds__(256) void k_bnfinal(const float* __restrict__ bg,
                                                 const float* __restrict__ bb) {
    int c = threadIdx.x;
    float mean = g_bnsum[c] * (1.f / NN);
    float var = g_bnsumsq[c] * (1.f / NN) - mean * mean;
    float sc = bg[c] * rsqrtf(var + 1e-5f);
    g_scale[c] = sc;
    g_shift[c] = bb[c] - mean * sc;
}

// ---------------- BN apply + ReLU + fused maxpool (330 -> 18) ----------------
__global__ __launch_bounds__(256) void k_pool() {
    int bt = blockIdx.x;
    int b = bt / 18, t = bt % 18;
    int c = threadIdx.x;
    float sc = g_scale[c], sh = g_shift[c];
    int base = b * 330 + t * 18;
    float mx = 0.f;
    #pragma unroll
    for (int n = 0; n < 18; n++) {
        float v = g_out[(base + n) * HID + c] * sc + sh;
        mx = fmaxf(mx, v);
    }
    g_pool[bt * HID + c] = mx;
}

// ---------------- head ----------------
__global__ __launch_bounds__(256) void k_head(const float* __restrict__ W1,
                                              const float* __restrict__ b1,
                                              const float* __restrict__ Wr) {
    __shared__ __align__(16) float row[HID];
    __shared__ float red[8];
    int bt = blockIdx.x;
    int b = bt / 18;
    int tid = threadIdx.x;
    row[tid] = g_pool[bt * HID + tid];
    __syncthreads();
    float acc = b1[tid];
    const float4* w4 = (const float4*)(W1 + tid * HID);
    const float4* r4 = (const float4*)row;
    #pragma unroll 8
    for (int j = 0; j < 64; j++) {
        float4 a = w4[j], r = r4[j];
        acc += a.x * r.x + a.y * r.y + a.z * r.z + a.w * r.w;
    }
    float h = fmaxf(acc, 0.f);
    float p = h * Wr[tid];
    #pragma unroll
    for (int o = 16; o; o >>= 1) p += __shfl_xor_sync(~0u, p, o);
    int wid = tid >> 5, lane = tid & 31;
    if (lane == 0) red[wid] = p;
    __syncthreads();
    if (tid == 0) {
        float tot = 0.f;
        #pragma unroll
        for (int i = 0; i < 8; i++) tot += red[i];
        atomicAdd(&g_bacc[b], tot);
    }
}

__global__ void k_final(const float* __restrict__ br, float* __restrict__ out) {
    int b = threadIdx.x;
    if (b < BB) {
        float c = g_bacc[b] * (1.f / 18.f) + br[0];
        out[b] = 1.f / (1.f + expf(-c));
    }
}

// ---------------- launch ----------------
extern "C" void kernel_launch(void* const* d_in, const int* in_sizes, int n_in,
                              void* d_out, int out_size) {
    const float* x   = (const float*)d_in[0];
    const int*   ei  = (const int*)  d_in[1];
    const float* ea  = (const float*)d_in[2];
    const float* Wq  = (const float*)d_in[4];
    const float* bq  = (const float*)d_in[5];
    const float* Wk  = (const float*)d_in[6];
    const float* bk  = (const float*)d_in[7];
    const float* Wv  = (const float*)d_in[8];
    const float* bv  = (const float*)d_in[9];
    const float* We  = (const float*)d_in[10];
    const float* Wsk = (const float*)d_in[11];
    const float* bsk = (const float*)d_in[12];
    const float* lg  = (const float*)d_in[13];
    const float* lb  = (const float*)d_in[14];
    const float* bg  = (const float*)d_in[15];
    const float* bb  = (const float*)d_in[16];
    const float* W1  = (const float*)d_in[17];
    const float* b1  = (const float*)d_in[18];
    const float* Wr  = (const float*)d_in[19];
    const float* br  = (const float*)d_in[20];
    float* out = (float*)d_out;

    k_init<<<128, 256>>>();
    k_count<<<(EE + 255) / 256, 256>>>(ei);
    k_scan<<<1, 1024>>>();
    k_fill<<<(EE + 255) / 256, 256>>>(ei);
    k_ln<<<NN, 128>>>(x, lg, lb);
    dim3 gg(8, NN / 32);
    k_gemm<<<gg, 128>>>(Wq, bq, Wk, bk, Wv, bv, Wsk, bsk);
    k_agg<<<(NN + 7) / 8, 256>>>(ea, We);
    k_bnstat<<<(NN + 31) / 32, 256>>>();
    k_bnfinal<<<1, 256>>>(bg, bb);
    k_pool<<<BB * 18, 256>>>();
    k_head<<<BB * 18, 256>>>(W1, b1, Wr);
    k_final<<<1, 64>>>(br, out);
}